// round 1
// baseline (speedup 1.0000x reference)
#include <cuda_runtime.h>

#define NB 32
#define TT 16384
#define HH 64
#define GG 192        // 3*H gate rows
#define CHUNK 192     // x prefetch chunk (== blockDim)

// ---- packed f32x2 helpers (Blackwell; only reachable via PTX) ----
__device__ __forceinline__ unsigned long long fma2(unsigned long long a,
                                                   unsigned long long b,
                                                   unsigned long long c) {
    unsigned long long d;
    asm("fma.rn.f32x2 %0, %1, %2, %3;" : "=l"(d) : "l"(a), "l"(b), "l"(c));
    return d;
}
__device__ __forceinline__ unsigned long long add2(unsigned long long a,
                                                   unsigned long long b) {
    unsigned long long d;
    asm("add.rn.f32x2 %0, %1, %2;" : "=l"(d) : "l"(a), "l"(b));
    return d;
}
__device__ __forceinline__ void unpack2(unsigned long long v, float& lo, float& hi) {
    asm("mov.b64 {%0, %1}, %2;" : "=f"(lo), "=f"(hi) : "l"(v));
}

__device__ __forceinline__ float sigmoid_f(float v) {
    // 1/(1+e^-v): MUFU.EX2 + MUFU.RCP path; safe at extremes (1/inf=0)
    return __fdividef(1.0f, 1.0f + __expf(-v));
}
__device__ __forceinline__ float tanh_f(float v) {
    // 2*sigmoid(2v)-1; no NaN at extremes (2/inf-1=-1)
    return fmaf(2.0f, __fdividef(1.0f, 1.0f + __expf(-2.0f * v)), -1.0f);
}

// ---------------------------------------------------------------------------
// Scan kernel: one block per batch element. Thread g in [0,192) owns gate row
// g of W_hh (64 weights, register-resident as 32 packed f32x2). Per step:
// all 192 threads compute gh[g] = W_hh[g,:].h + b_hh[g] via packed FMA,
// then threads [0,64) do the gate nonlinearity + state update.
// ---------------------------------------------------------------------------
__global__ void __launch_bounds__(GG, 1) gru_scan_kernel(
    const float* __restrict__ x,
    const float* __restrict__ W_ih,
    const float* __restrict__ W_hh,
    const float* __restrict__ b_ih,
    const float* __restrict__ b_hh,
    float* __restrict__ states)
{
    const int b = blockIdx.x;
    const int g = threadIdx.x;

    __shared__ float h_sh[HH];
    __shared__ float gh_sh[GG];
    __shared__ float x_sh[2][CHUNK];

    // Pack this thread's W_hh row into registers (row is 256B aligned).
    unsigned long long w[32];
    {
        const ulonglong2* wr = (const ulonglong2*)(W_hh + (size_t)g * HH);
        #pragma unroll
        for (int j = 0; j < 16; j++) {
            ulonglong2 v = wr[j];
            w[2 * j]     = v.x;
            w[2 * j + 1] = v.y;
        }
    }
    const float bhh = b_hh[g];

    // Gate-thread constants (input projection is a scalar FMA since CIN=1).
    float wir = 0.f, wiz = 0.f, win = 0.f, bir = 0.f, biz = 0.f, bin = 0.f;
    if (g < HH) {
        wir = W_ih[g];          bir = b_ih[g];
        wiz = W_ih[HH + g];     biz = b_ih[HH + g];
        win = W_ih[2 * HH + g]; bin = b_ih[2 * HH + g];
        h_sh[g] = 0.0f;
    }

    const float* xb = x + (size_t)b * TT;
    x_sh[0][g] = xb[g];                 // chunk 0
    __syncthreads();

    float h_reg = 0.0f;                 // thread i<64 carries h[i] privately
    float xnext = 0.0f;
    int tmod = 0, buf = 0;
    float* st_base = states + (size_t)b * TT * HH;

    for (int t = 0; t < TT; t++) {
        // x double-buffer: issue LDG at chunk start, commit to the other
        // buffer mid-chunk (96 steps of latency slack).
        if (tmod == 0) {
            int tn = t + CHUNK;
            if (tn < TT) xnext = xb[tn + g];
        } else if (tmod == CHUNK / 2) {
            if (t + CHUNK / 2 < TT) x_sh[buf ^ 1][g] = xnext;
        }

        // gh[g] = dot(W_hh[g,:], h) + b_hh[g] with packed f32x2 FMAs.
        const ulonglong2* hp = (const ulonglong2*)h_sh;
        unsigned long long a0 = 0ull, a1 = 0ull, a2 = 0ull, a3 = 0ull;
        #pragma unroll
        for (int j = 0; j < 16; j += 2) {
            ulonglong2 v0 = hp[j];       // broadcast LDS.128, conflict-free
            ulonglong2 v1 = hp[j + 1];
            a0 = fma2(w[2 * j],     v0.x, a0);
            a1 = fma2(w[2 * j + 1], v0.y, a1);
            a2 = fma2(w[2 * j + 2], v1.x, a2);
            a3 = fma2(w[2 * j + 3], v1.y, a3);
        }
        unsigned long long s = add2(add2(a0, a1), add2(a2, a3));
        float lo, hi;
        unpack2(s, lo, hi);
        gh_sh[g] = lo + hi + bhh;
        __syncthreads();

        if (g < HH) {
            float xt = x_sh[buf][tmod];
            float pr = fmaf(xt, wir, bir) + gh_sh[g];
            float pz = fmaf(xt, wiz, biz) + gh_sh[HH + g];
            float r = sigmoid_f(pr);
            float z = sigmoid_f(pz);
            float pn = fmaf(xt, win, bin) + r * gh_sh[2 * HH + g];
            float n = tanh_f(pn);
            h_reg = n + z * (h_reg - n);     // (1-z)*n + z*h
            h_sh[g] = h_reg;
            st_base[(size_t)t * HH + g] = h_reg;   // coalesced 256B
        }
        __syncthreads();

        if (++tmod == CHUNK) { tmod = 0; buf ^= 1; }
    }
}

// ---------------------------------------------------------------------------
// Head: out[b,t] = states[b,t,:].W_out + b_out + x[b,t]. One warp per (b,t),
// grid-stride. Pure streaming pass (~134MB read), memory-bound.
// ---------------------------------------------------------------------------
__global__ void head_kernel(const float* __restrict__ states,
                            const float* __restrict__ x,
                            const float* __restrict__ W_out,
                            const float* __restrict__ b_out,
                            float* __restrict__ out)
{
    const int lane = threadIdx.x & 31;
    const int warp = (int)((blockIdx.x * blockDim.x + threadIdx.x) >> 5);
    const int nw = (int)((gridDim.x * blockDim.x) >> 5);
    const float w0 = W_out[lane];
    const float w1 = W_out[32 + lane];
    const float bo = b_out[0];
    const long total = (long)NB * TT;
    for (long i = warp; i < total; i += nw) {
        const float* s = states + (size_t)i * HH;
        float p = fmaf(s[lane], w0, s[lane + 32] * w1);
        #pragma unroll
        for (int o = 16; o > 0; o >>= 1)
            p += __shfl_xor_sync(0xffffffffu, p, o);
        if (lane == 0) out[i] = p + bo + x[i];
    }
}

extern "C" void kernel_launch(void* const* d_in, const int* in_sizes, int n_in,
                              void* d_out, int out_size) {
    const float* x     = (const float*)d_in[0];
    const float* W_ih  = (const float*)d_in[1];
    const float* W_hh  = (const float*)d_in[2];
    const float* b_ih  = (const float*)d_in[3];
    const float* b_hh  = (const float*)d_in[4];
    const float* W_out = (const float*)d_in[5];
    const float* b_out = (const float*)d_in[6];

    float* out    = (float*)d_out;              // [B*T]   (tuple elem 0)
    float* states = out + (size_t)NB * TT;      // [B*T*H] (tuple elem 1)

    gru_scan_kernel<<<NB, GG>>>(x, W_ih, W_hh, b_ih, b_hh, states);
    head_kernel<<<512, 256>>>(states, x, W_out, b_out, out);
}

// round 2
// speedup vs baseline: 1.2324x; 1.2324x over previous
#include <cuda_runtime.h>

#define NB 32
#define TT 16384
#define HH 64
#define GG 192         // 3*H gate rows; blockDim
#define XCHUNK 64      // x prefetch chunk (== #gate threads)

// ---- packed f32x2 helpers (Blackwell; only reachable via PTX) ----
__device__ __forceinline__ unsigned long long fma2(unsigned long long a,
                                                   unsigned long long b,
                                                   unsigned long long c) {
    unsigned long long d;
    asm("fma.rn.f32x2 %0, %1, %2, %3;" : "=l"(d) : "l"(a), "l"(b), "l"(c));
    return d;
}
__device__ __forceinline__ unsigned long long add2(unsigned long long a,
                                                   unsigned long long b) {
    unsigned long long d;
    asm("add.rn.f32x2 %0, %1, %2;" : "=l"(d) : "l"(a), "l"(b));
    return d;
}
__device__ __forceinline__ void unpack2(unsigned long long v, float& lo, float& hi) {
    asm("mov.b64 {%0, %1}, %2;" : "=f"(lo), "=f"(hi) : "l"(v));
}

__device__ __forceinline__ float sigmoid_f(float v) {
    return __fdividef(1.0f, 1.0f + __expf(-v));
}
__device__ __forceinline__ float tanh_f(float v) {
    return fmaf(2.0f, __fdividef(1.0f, 1.0f + __expf(-2.0f * v)), -1.0f);
}

// named barriers (memory clobber forces reload of h_sh/gh_sh across phases)
#define NBAR_SYNC(id, cnt) \
    asm volatile("bar.sync %0, %1;" :: "r"(id), "r"(cnt) : "memory")
#define NBAR_ARRIVE(id, cnt) \
    asm volatile("bar.arrive %0, %1;" :: "r"(id), "r"(cnt) : "memory")

// 64-wide dot of register-resident packed row w[32] with h_sh (broadcast LDS.128)
__device__ __forceinline__ float dot_h(const unsigned long long* w,
                                       const float* h_sh) {
    const ulonglong2* hp = (const ulonglong2*)h_sh;
    unsigned long long a0 = 0ull, a1 = 0ull, a2 = 0ull, a3 = 0ull;
    #pragma unroll
    for (int j = 0; j < 16; j += 2) {
        ulonglong2 v0 = hp[j];
        ulonglong2 v1 = hp[j + 1];
        a0 = fma2(w[2 * j],     v0.x, a0);
        a1 = fma2(w[2 * j + 1], v0.y, a1);
        a2 = fma2(w[2 * j + 2], v1.x, a2);
        a3 = fma2(w[2 * j + 3], v1.y, a3);
    }
    unsigned long long s = add2(add2(a0, a1), add2(a2, a3));
    float lo, hi;
    unpack2(s, lo, hi);
    return lo + hi;
}

// ---------------------------------------------------------------------------
// Warp-specialized scan. One block per batch.
//   threads [0,64)   : gate warps — own r-gate rows (0..63) AND the state
//                      update. r is computed locally, overlapped with the
//                      producers' dot phase, so only z/n cross the barrier.
//   threads [64,192) : producer warps — z rows (64..127), n rows (128..191);
//                      publish gh = dot + b_hh and immediately wait for next h.
// Barriers: bar1 (gh ready: producers arrive, gates sync, count 192)
//           bar3 (h ready:  gates arrive, producers sync, count 192)
//           bar2 (h visible among the two gate warps, count 64)
// ---------------------------------------------------------------------------
__global__ void __launch_bounds__(GG, 1) gru_scan_kernel(
    const float* __restrict__ x,
    const float* __restrict__ W_ih,
    const float* __restrict__ W_hh,
    const float* __restrict__ b_ih,
    const float* __restrict__ b_hh,
    float* __restrict__ states)
{
    const int b = blockIdx.x;
    const int g = threadIdx.x;

    __shared__ float h_sh[HH];
    __shared__ float gh_sh[GG];          // rows 64..191 used
    __shared__ float x_sh[2][XCHUNK];

    // Register-resident W_hh row g (256B, aligned).
    unsigned long long w[32];
    {
        const ulonglong2* wr = (const ulonglong2*)(W_hh + (size_t)g * HH);
        #pragma unroll
        for (int j = 0; j < 16; j++) {
            ulonglong2 v = wr[j];
            w[2 * j]     = v.x;
            w[2 * j + 1] = v.y;
        }
    }
    const float bhh = b_hh[g];

    const float* xb = x + (size_t)b * TT;
    float* st_base = states + (size_t)b * TT * HH;

    if (g < HH) {
        h_sh[g] = 0.0f;
        x_sh[0][g] = xb[g];
    }
    __syncthreads();

    if (g < HH) {
        // ---------------- gate warps ----------------
        const float wir = W_ih[g],          bir = b_ih[g];
        const float wiz = W_ih[HH + g],     biz = b_ih[HH + g];
        const float win = W_ih[2 * HH + g], bin = b_ih[2 * HH + g];
        float h = 0.0f, xnext = 0.0f;
        int tmod = 0, buf = 0;

        for (int t = 0; t < TT; t++) {
            // x double-buffer (gates only): LDG at chunk start, commit mid-chunk
            if (tmod == 0) {
                int tn = t + XCHUNK;
                if (tn < TT) xnext = xb[tn + g];
            } else if (tmod == XCHUNK / 2) {
                if (t + XCHUNK / 2 < TT) x_sh[buf ^ 1][g] = xnext;
            }
            const float xt = x_sh[buf][tmod];

            // r-gate: local dot, overlapped with producers' dot phase
            const float rdot = dot_h(w, h_sh);
            const float r = sigmoid_f(fmaf(xt, wir, bir) + rdot + bhh);
            const float xpn = fmaf(xt, win, bin);
            const float xpz = fmaf(xt, wiz, biz);

            NBAR_SYNC(1, GG);                    // wait z/n gh
            const float ghz = gh_sh[HH + g];
            const float ghn = gh_sh[2 * HH + g];
            const float z = sigmoid_f(xpz + ghz);
            const float n = tanh_f(fmaf(r, ghn, xpn));
            h = n + z * (h - n);                 // (1-z)*n + z*h

            h_sh[g] = h;
            st_base[(size_t)t * HH + g] = h;     // coalesced 256B, off-path
            NBAR_ARRIVE(3, GG);                  // release producers
            NBAR_SYNC(2, HH);                    // h visible among gate warps

            if (++tmod == XCHUNK) { tmod = 0; buf ^= 1; }
        }
    } else {
        // ---------------- producer warps ----------------
        for (int t = 0; t < TT; t++) {
            const float d = dot_h(w, h_sh);
            gh_sh[g] = d + bhh;
            NBAR_ARRIVE(1, GG);                  // gh published
            NBAR_SYNC(3, GG);                    // wait next h
        }
    }
}

// ---------------------------------------------------------------------------
// Head: out[b,t] = states[b,t,:].W_out + b_out + x[b,t]. One warp per (b,t).
// 61us measured, ~1% of total — not worth touching yet.
// ---------------------------------------------------------------------------
__global__ void head_kernel(const float* __restrict__ states,
                            const float* __restrict__ x,
                            const float* __restrict__ W_out,
                            const float* __restrict__ b_out,
                            float* __restrict__ out)
{
    const int lane = threadIdx.x & 31;
    const int warp = (int)((blockIdx.x * blockDim.x + threadIdx.x) >> 5);
    const int nw = (int)((gridDim.x * blockDim.x) >> 5);
    const float w0 = W_out[lane];
    const float w1 = W_out[32 + lane];
    const float bo = b_out[0];
    const long total = (long)NB * TT;
    for (long i = warp; i < total; i += nw) {
        const float* s = states + (size_t)i * HH;
        float p = fmaf(s[lane], w0, s[lane + 32] * w1);
        #pragma unroll
        for (int o = 16; o > 0; o >>= 1)
            p += __shfl_xor_sync(0xffffffffu, p, o);
        if (lane == 0) out[i] = p + bo + x[i];
    }
}

extern "C" void kernel_launch(void* const* d_in, const int* in_sizes, int n_in,
                              void* d_out, int out_size) {
    const float* x     = (const float*)d_in[0];
    const float* W_ih  = (const float*)d_in[1];
    const float* W_hh  = (const float*)d_in[2];
    const float* b_ih  = (const float*)d_in[3];
    const float* b_hh  = (const float*)d_in[4];
    const float* W_out = (const float*)d_in[5];
    const float* b_out = (const float*)d_in[6];

    float* out    = (float*)d_out;              // [B*T]   (tuple elem 0)
    float* states = out + (size_t)NB * TT;      // [B*T*H] (tuple elem 1)

    gru_scan_kernel<<<NB, GG>>>(x, W_ih, W_hh, b_ih, b_hh, states);
    head_kernel<<<512, 256>>>(states, x, W_out, b_out, out);
}

// round 3
// speedup vs baseline: 1.2486x; 1.0132x over previous
#include <cuda_runtime.h>

#define NB 32
#define TT 16384
#define HH 64
#define GG 192         // 3*H gate rows; blockDim
#define XCHUNK 64      // x prefetch chunk (== #gate threads)

// ---- packed f32x2 helpers (Blackwell; only reachable via PTX) ----
__device__ __forceinline__ unsigned long long fma2(unsigned long long a,
                                                   unsigned long long b,
                                                   unsigned long long c) {
    unsigned long long d;
    asm("fma.rn.f32x2 %0, %1, %2, %3;" : "=l"(d) : "l"(a), "l"(b), "l"(c));
    return d;
}
__device__ __forceinline__ unsigned long long add2(unsigned long long a,
                                                   unsigned long long b) {
    unsigned long long d;
    asm("add.rn.f32x2 %0, %1, %2;" : "=l"(d) : "l"(a), "l"(b));
    return d;
}
__device__ __forceinline__ void unpack2(unsigned long long v, float& lo, float& hi) {
    asm("mov.b64 {%0, %1}, %2;" : "=f"(lo), "=f"(hi) : "l"(v));
}
__device__ __forceinline__ unsigned long long pack2(float lo, float hi) {
    unsigned long long v;
    asm("mov.b64 %0, {%1, %2};" : "=l"(v) : "f"(lo), "f"(hi));
    return v;
}

__device__ __forceinline__ float sigmoid_f(float v) {
    return __fdividef(1.0f, 1.0f + __expf(-v));
}
__device__ __forceinline__ float tanh_f(float v) {
    return fmaf(2.0f, __fdividef(1.0f, 1.0f + __expf(-2.0f * v)), -1.0f);
}

// named barriers (memory clobber forces smem reload across phases)
#define NBAR_SYNC(id, cnt) \
    asm volatile("bar.sync %0, %1;" :: "r"(id), "r"(cnt) : "memory")
#define NBAR_ARRIVE(id, cnt) \
    asm volatile("bar.arrive %0, %1;" :: "r"(id), "r"(cnt) : "memory")

// 64-wide dot of register-resident packed row w[32] with h_sh.
// 8 accumulators (dep depth 4), bias folded into a0.
__device__ __forceinline__ float dot_h(const unsigned long long* w,
                                       const float* h_sh, float bias) {
    const ulonglong2* hp = (const ulonglong2*)h_sh;
    unsigned long long a0 = pack2(bias, 0.0f);
    unsigned long long a1 = 0ull, a2 = 0ull, a3 = 0ull;
    unsigned long long a4 = 0ull, a5 = 0ull, a6 = 0ull, a7 = 0ull;
    #pragma unroll
    for (int j = 0; j < 16; j += 4) {
        ulonglong2 v0 = hp[j];
        ulonglong2 v1 = hp[j + 1];
        ulonglong2 v2 = hp[j + 2];
        ulonglong2 v3 = hp[j + 3];
        a0 = fma2(w[2 * j],     v0.x, a0);
        a1 = fma2(w[2 * j + 1], v0.y, a1);
        a2 = fma2(w[2 * j + 2], v1.x, a2);
        a3 = fma2(w[2 * j + 3], v1.y, a3);
        a4 = fma2(w[2 * j + 4], v2.x, a4);
        a5 = fma2(w[2 * j + 5], v2.y, a5);
        a6 = fma2(w[2 * j + 6], v3.x, a6);
        a7 = fma2(w[2 * j + 7], v3.y, a7);
    }
    unsigned long long s =
        add2(add2(add2(a0, a1), add2(a2, a3)),
             add2(add2(a4, a5), add2(a6, a7)));
    float lo, hi;
    unpack2(s, lo, hi);
    return lo + hi;
}

// ---------------------------------------------------------------------------
// Warp-specialized scan. One block per batch.
//   threads [0,64)   : gate warps — r-gate rows (dot + sigmoid computed
//                      locally, overlapped with producers) + state update.
//   threads [64,192) : producer warps — z rows (64..127), n rows (128..191);
//                      publish gh interleaved as float2 {z,n} per h-index.
// Barriers: bar1 (gh ready: producers arrive, gates sync, count 192)
//           bar3 (h ready: full bar.sync by all 192 — doubles as the
//                 intra-gate-warp h exchange; bar2 eliminated)
// ---------------------------------------------------------------------------
__global__ void __launch_bounds__(GG, 1) gru_scan_kernel(
    const float* __restrict__ x,
    const float* __restrict__ W_ih,
    const float* __restrict__ W_hh,
    const float* __restrict__ b_ih,
    const float* __restrict__ b_hh,
    float* __restrict__ states)
{
    const int b = blockIdx.x;
    const int g = threadIdx.x;

    __shared__ float h_sh[HH];
    __shared__ float2 zn_sh[HH];         // .x = gh_z, .y = gh_n per h-index
    __shared__ float x_sh[2][XCHUNK];

    // Register-resident W_hh row g (256B, aligned).
    unsigned long long w[32];
    {
        const ulonglong2* wr = (const ulonglong2*)(W_hh + (size_t)g * HH);
        #pragma unroll
        for (int j = 0; j < 16; j++) {
            ulonglong2 v = wr[j];
            w[2 * j]     = v.x;
            w[2 * j + 1] = v.y;
        }
    }
    const float bhh = b_hh[g];

    const float* xb = x + (size_t)b * TT;
    float* st_base = states + (size_t)b * TT * HH;

    if (g < HH) {
        h_sh[g] = 0.0f;
        x_sh[0][g] = xb[g];
    }
    __syncthreads();

    if (g < HH) {
        // ---------------- gate warps ----------------
        const float wir = W_ih[g],          bir = b_ih[g];
        const float wiz = W_ih[HH + g],     biz = b_ih[HH + g];
        const float win = W_ih[2 * HH + g], bin = b_ih[2 * HH + g];
        float h = 0.0f, xnext = 0.0f;
        int tmod = 0, buf = 0;

        for (int t = 0; t < TT; t++) {
            // x double-buffer: LDG at chunk start, commit mid-chunk
            if (tmod == 0) {
                int tn = t + XCHUNK;
                if (tn < TT) xnext = xb[tn + g];
            } else if (tmod == XCHUNK / 2) {
                if (t + XCHUNK / 2 < TT) x_sh[buf ^ 1][g] = xnext;
            }
            const float xt = x_sh[buf][tmod];

            // r-gate: local dot + sigmoid, overlapped with producers' dots
            const float r = sigmoid_f(fmaf(xt, wir, bir) + dot_h(w, h_sh, bhh));
            const float xpn = fmaf(xt, win, bin);
            const float xpz = fmaf(xt, wiz, biz);

            NBAR_SYNC(1, GG);                    // wait z/n gh
            const float2 zn = zn_sh[g];          // one LDS.64
            const float z = sigmoid_f(xpz + zn.x);
            const float n = tanh_f(fmaf(r, zn.y, xpn));
            h = n + z * (h - n);                 // (1-z)*n + z*h

            h_sh[g] = h;
            st_base[(size_t)t * HH + g] = h;     // coalesced 256B, off-path
            NBAR_SYNC(3, GG);                    // full barrier: h visible to
                                                 // producers AND peer gate warp
            if (++tmod == XCHUNK) { tmod = 0; buf ^= 1; }
        }
    } else if (g < 2 * HH) {
        // ---------------- z producers ----------------
        const int i = g - HH;
        for (int t = 0; t < TT; t++) {
            zn_sh[i].x = dot_h(w, h_sh, bhh);
            NBAR_ARRIVE(1, GG);
            NBAR_SYNC(3, GG);
        }
    } else {
        // ---------------- n producers ----------------
        const int i = g - 2 * HH;
        for (int t = 0; t < TT; t++) {
            zn_sh[i].y = dot_h(w, h_sh, bhh);
            NBAR_ARRIVE(1, GG);
            NBAR_SYNC(3, GG);
        }
    }
}

// ---------------------------------------------------------------------------
// Head: out[b,t] = states[b,t,:].W_out + b_out + x[b,t]. One warp per (b,t).
// ---------------------------------------------------------------------------
__global__ void head_kernel(const float* __restrict__ states,
                            const float* __restrict__ x,
                            const float* __restrict__ W_out,
                            const float* __restrict__ b_out,
                            float* __restrict__ out)
{
    const int lane = threadIdx.x & 31;
    const int warp = (int)((blockIdx.x * blockDim.x + threadIdx.x) >> 5);
    const int nw = (int)((gridDim.x * blockDim.x) >> 5);
    const float w0 = W_out[lane];
    const float w1 = W_out[32 + lane];
    const float bo = b_out[0];
    const long total = (long)NB * TT;
    for (long i = warp; i < total; i += nw) {
        const float* s = states + (size_t)i * HH;
        float p = fmaf(s[lane], w0, s[lane + 32] * w1);
        #pragma unroll
        for (int o = 16; o > 0; o >>= 1)
            p += __shfl_xor_sync(0xffffffffu, p, o);
        if (lane == 0) out[i] = p + bo + x[i];
    }
}

// Empty kernel: shifts launch parity so ncu's "-s 5 -c 1" profiles the SCAN
// kernel (launch order per call: nop, scan, head, nop -> scan at idx 1,5,9...)
__global__ void nop_kernel() {}

extern "C" void kernel_launch(void* const* d_in, const int* in_sizes, int n_in,
                              void* d_out, int out_size) {
    const float* x     = (const float*)d_in[0];
    const float* W_ih  = (const float*)d_in[1];
    const float* W_hh  = (const float*)d_in[2];
    const float* b_ih  = (const float*)d_in[3];
    const float* b_hh  = (const float*)d_in[4];
    const float* W_out = (const float*)d_in[5];
    const float* b_out = (const float*)d_in[6];

    float* out    = (float*)d_out;              // [B*T]   (tuple elem 0)
    float* states = out + (size_t)NB * TT;      // [B*T*H] (tuple elem 1)

    nop_kernel<<<1, 32>>>();
    gru_scan_kernel<<<NB, GG>>>(x, W_ih, W_hh, b_ih, b_hh, states);
    head_kernel<<<512, 256>>>(states, x, W_out, b_out, out);
    nop_kernel<<<1, 32>>>();
}